// round 1
// baseline (speedup 1.0000x reference)
#include <cuda_runtime.h>

#define BB 2
#define SS 2048
#define DD 2048
#define HH 16
#define HD 128
#define HD2 64
#define MM (BB*SS)

// Scratch (device globals: allocation-free per harness rules)
__device__ float g_Q[(size_t)MM * DD];
__device__ float g_K[(size_t)MM * DD];
__device__ float g_V[(size_t)MM * DD];
__device__ float g_AO[(size_t)MM * DD];

// ---------------------------------------------------------------------------
// GEMM: C[M,N] = A[M,K] @ W[N,K]^T   (M=4096, N=K=2048)
// 128x128 tile, BK=16, 256 threads, 8x8 per thread.
// ROT: fuse rotary embedding into epilogue (Q/K projections).
// ---------------------------------------------------------------------------
template<bool ROT>
__global__ __launch_bounds__(256)
void gemm_nt_kernel(const float* __restrict__ A, const float* __restrict__ W,
                    float* __restrict__ C,
                    const float* __restrict__ fc, const float* __restrict__ fs)
{
    __shared__ float As[16][132];
    __shared__ float Bs[16][132];

    const int t    = threadIdx.x;
    const int row0 = blockIdx.y * 128;
    const int col0 = blockIdx.x * 128;

    // loader coords: each thread loads 2 float4 of A and 2 of W per k-tile
    const int lr = t >> 2;            // 0..63
    const int lc = (t & 3) << 2;      // 0,4,8,12
    const float* Ap = A + (size_t)(row0 + lr) * DD + lc;
    const float* Wp = W + (size_t)(col0 + lr) * DD + lc;

    // compute coords
    const int ry = (t >> 4) << 3;     // 0..120, step 8
    const int rx = (t & 15) << 3;     // 0..120, step 8

    float acc[8][8];
#pragma unroll
    for (int i = 0; i < 8; i++)
#pragma unroll
        for (int j = 0; j < 8; j++) acc[i][j] = 0.f;

    for (int kk = 0; kk < DD; kk += 16) {
        float4 a0 = *(const float4*)(Ap + kk);
        float4 a1 = *(const float4*)(Ap + kk + (size_t)64 * DD);
        float4 b0 = *(const float4*)(Wp + kk);
        float4 b1 = *(const float4*)(Wp + kk + (size_t)64 * DD);

        __syncthreads();
        As[lc+0][lr]    = a0.x; As[lc+1][lr]    = a0.y; As[lc+2][lr]    = a0.z; As[lc+3][lr]    = a0.w;
        As[lc+0][lr+64] = a1.x; As[lc+1][lr+64] = a1.y; As[lc+2][lr+64] = a1.z; As[lc+3][lr+64] = a1.w;
        Bs[lc+0][lr]    = b0.x; Bs[lc+1][lr]    = b0.y; Bs[lc+2][lr]    = b0.z; Bs[lc+3][lr]    = b0.w;
        Bs[lc+0][lr+64] = b1.x; Bs[lc+1][lr+64] = b1.y; Bs[lc+2][lr+64] = b1.z; Bs[lc+3][lr+64] = b1.w;
        __syncthreads();

#pragma unroll
        for (int k = 0; k < 16; k++) {
            float4 a40 = *(const float4*)&As[k][ry];
            float4 a41 = *(const float4*)&As[k][ry + 4];
            float4 b40 = *(const float4*)&Bs[k][rx];
            float4 b41 = *(const float4*)&Bs[k][rx + 4];
            float av[8] = {a40.x, a40.y, a40.z, a40.w, a41.x, a41.y, a41.z, a41.w};
            float bv[8] = {b40.x, b40.y, b40.z, b40.w, b41.x, b41.y, b41.z, b41.w};
#pragma unroll
            for (int i = 0; i < 8; i++)
#pragma unroll
                for (int j = 0; j < 8; j++)
                    acc[i][j] += av[i] * bv[j];
        }
    }

    if (ROT) {
#pragma unroll
        for (int i = 0; i < 8; i++) {
            const int gm = row0 + ry + i;
            const int s  = gm & (SS - 1);          // row = b*S + s
            const float* fcr = fc + (size_t)s * HD2;
            const float* fsr = fs + (size_t)s * HD2;
            float* Crow = C + (size_t)gm * DD;
#pragma unroll
            for (int jp = 0; jp < 4; jp++) {
                const int col = col0 + rx + jp * 2;
                const int p   = (col & (HD - 1)) >> 1;
                const float c  = fcr[p];
                const float sn = fsr[p];
                const float v0 = acc[i][2 * jp];
                const float v1 = acc[i][2 * jp + 1];
                Crow[col]     = v0 * c - v1 * sn;
                Crow[col + 1] = v0 * sn + v1 * c;
            }
        }
    } else {
#pragma unroll
        for (int i = 0; i < 8; i++) {
            const int gm = row0 + ry + i;
            float* Crow = C + (size_t)gm * DD + (col0 + rx);
            float4 w0 = make_float4(acc[i][0], acc[i][1], acc[i][2], acc[i][3]);
            float4 w1 = make_float4(acc[i][4], acc[i][5], acc[i][6], acc[i][7]);
            *(float4*)(Crow)     = w0;
            *(float4*)(Crow + 4) = w1;
        }
    }
}

// ---------------------------------------------------------------------------
// Causal flash attention, fp32. One CTA per (q_tile of 64, b*h).
// K/V tiles of 64 rows. 256 threads: 16x16, each owns 4 rows x 8 out-cols.
// Dynamic smem layout (floats):
//   Qs[128][64] (c-major)  Ks[128][64] (c-major)  Vs[64][128]
//   Ps[64][64] ([k][row])  Ss[64][65] ([row][k])  ms[64] ls[64] al[64]
// ---------------------------------------------------------------------------
#define FLASH_SMEM_FLOATS (128*64 + 128*64 + 64*128 + 64*64 + 64*65 + 192)
#define FLASH_SMEM_BYTES  (FLASH_SMEM_FLOATS * 4)

__global__ __launch_bounds__(256)
void flash_kernel(const float* __restrict__ Q, const float* __restrict__ K,
                  const float* __restrict__ V, float* __restrict__ O)
{
    extern __shared__ float sm[];
    float* Qs = sm;                 // [c][r] 128*64
    float* Ks = Qs + 128 * 64;      // [c][r] 128*64
    float* Vs = Ks + 128 * 64;      // [r][c] 64*128
    float* Ps = Vs + 64 * 128;      // [k][r] 64*64
    float* Ss = Ps + 64 * 64;       // [r][k] 64*65 (padded)
    float* ms = Ss + 64 * 65;
    float* ls = ms + 64;
    float* al = ls + 64;

    const int t  = threadIdx.x;
    const int qt = blockIdx.x;
    const int bh = blockIdx.y;
    const int b  = bh >> 4, h = bh & 15;
    const int q0 = qt * 64;

    const size_t headoff = (size_t)b * SS * DD + (size_t)h * HD;
    const float* Qp = Q + headoff;
    const float* Kp = K + headoff;
    const float* Vp = V + headoff;
    float*       Op = O + headoff;

    const int ty = t >> 4, tx = t & 15;
    const int ry = ty << 2;      // 4-row group
    const int rx = tx << 2;      // 4-key-col group (S phase)
    const int cb = tx << 3;      // 8-col group (O phase)

    // Load Q tile transposed: Qs[c][r]
    for (int f = t; f < 2048; f += 256) {
        const int r  = f >> 5;
        const int cv = (f & 31) << 2;
        float4 v = *(const float4*)(Qp + (size_t)(q0 + r) * DD + cv);
        Qs[(cv + 0) * 64 + r] = v.x;
        Qs[(cv + 1) * 64 + r] = v.y;
        Qs[(cv + 2) * 64 + r] = v.z;
        Qs[(cv + 3) * 64 + r] = v.w;
    }
    if (t < 64) { ms[t] = -1e30f; ls[t] = 0.f; }

    float o[4][8];
#pragma unroll
    for (int i = 0; i < 4; i++)
#pragma unroll
        for (int j = 0; j < 8; j++) o[i][j] = 0.f;

    const float scale = 0.08838834764831845f;   // 1/sqrt(128)

    for (int kt = 0; kt <= qt; kt++) {
        const int k0 = kt * 64;
        // Load K (transposed) and V (direct) tiles
        for (int f = t; f < 2048; f += 256) {
            const int r  = f >> 5;
            const int cv = (f & 31) << 2;
            float4 kv = *(const float4*)(Kp + (size_t)(k0 + r) * DD + cv);
            Ks[(cv + 0) * 64 + r] = kv.x;
            Ks[(cv + 1) * 64 + r] = kv.y;
            Ks[(cv + 2) * 64 + r] = kv.z;
            Ks[(cv + 3) * 64 + r] = kv.w;
            float4 vv = *(const float4*)(Vp + (size_t)(k0 + r) * DD + cv);
            *(float4*)&Vs[r * 128 + cv] = vv;
        }
        __syncthreads();

        // S = Q @ K^T (64x64), each thread 4x4
        float s[4][4];
#pragma unroll
        for (int i = 0; i < 4; i++)
#pragma unroll
            for (int j = 0; j < 4; j++) s[i][j] = 0.f;

#pragma unroll 4
        for (int c = 0; c < 128; c++) {
            float4 q4 = *(const float4*)&Qs[c * 64 + ry];
            float4 k4 = *(const float4*)&Ks[c * 64 + rx];
            float qa[4] = {q4.x, q4.y, q4.z, q4.w};
            float ka[4] = {k4.x, k4.y, k4.z, k4.w};
#pragma unroll
            for (int i = 0; i < 4; i++)
#pragma unroll
                for (int j = 0; j < 4; j++)
                    s[i][j] += qa[i] * ka[j];
        }

        const bool diag = (kt == qt);
#pragma unroll
        for (int i = 0; i < 4; i++)
#pragma unroll
            for (int j = 0; j < 4; j++) {
                float v = s[i][j] * scale;
                if (diag && (rx + j) > (ry + i)) v = -1e30f;
                Ss[(ry + i) * 65 + (rx + j)] = v;
            }
        __syncthreads();

        // Online softmax per row (64 owner threads)
        if (t < 64) {
            const float* srow = &Ss[t * 65];
            float mo = ms[t];
            float mx = mo;
#pragma unroll 8
            for (int j = 0; j < 64; j++) mx = fmaxf(mx, srow[j]);
            const float a = __expf(mo - mx);
            float l = ls[t] * a;
#pragma unroll 8
            for (int j = 0; j < 64; j++) {
                const float p = __expf(srow[j] - mx);
                l += p;
                Ps[j * 64 + t] = p;
            }
            ms[t] = mx; ls[t] = l; al[t] = a;
        }
        __syncthreads();

        // O = O*alpha + P @ V, each thread 4 rows x 8 cols
        float af[4];
#pragma unroll
        for (int i = 0; i < 4; i++) af[i] = al[ry + i];
#pragma unroll
        for (int i = 0; i < 4; i++)
#pragma unroll
            for (int j = 0; j < 8; j++) o[i][j] *= af[i];

#pragma unroll 4
        for (int k = 0; k < 64; k++) {
            float4 p4 = *(const float4*)&Ps[k * 64 + ry];
            float4 v0 = *(const float4*)&Vs[k * 128 + cb];
            float4 v1 = *(const float4*)&Vs[k * 128 + cb + 4];
            float pa[4] = {p4.x, p4.y, p4.z, p4.w};
            float va[8] = {v0.x, v0.y, v0.z, v0.w, v1.x, v1.y, v1.z, v1.w};
#pragma unroll
            for (int i = 0; i < 4; i++)
#pragma unroll
                for (int j = 0; j < 8; j++)
                    o[i][j] += pa[i] * va[j];
        }
        __syncthreads();   // protect Ks/Vs/Ss/Ps before next iteration
    }

    // Epilogue: divide by l, store
    float inv[4];
#pragma unroll
    for (int i = 0; i < 4; i++) inv[i] = 1.f / ls[ry + i];
#pragma unroll
    for (int i = 0; i < 4; i++) {
        float* dst = Op + (size_t)(q0 + ry + i) * DD + cb;
        float4 w0 = make_float4(o[i][0] * inv[i], o[i][1] * inv[i],
                                o[i][2] * inv[i], o[i][3] * inv[i]);
        float4 w1 = make_float4(o[i][4] * inv[i], o[i][5] * inv[i],
                                o[i][6] * inv[i], o[i][7] * inv[i]);
        *(float4*)(dst)     = w0;
        *(float4*)(dst + 4) = w1;
    }
}

// ---------------------------------------------------------------------------
extern "C" void kernel_launch(void* const* d_in, const int* in_sizes, int n_in,
                              void* d_out, int out_size)
{
    const float* x  = (const float*)d_in[0];
    const float* fc = (const float*)d_in[1];
    const float* fs = (const float*)d_in[2];
    const float* wq = (const float*)d_in[3];
    const float* wk = (const float*)d_in[4];
    const float* wv = (const float*)d_in[5];
    const float* wo = (const float*)d_in[6];
    float* out = (float*)d_out;

    float *Q, *K, *V, *AO;
    cudaGetSymbolAddress((void**)&Q,  g_Q);
    cudaGetSymbolAddress((void**)&K,  g_K);
    cudaGetSymbolAddress((void**)&V,  g_V);
    cudaGetSymbolAddress((void**)&AO, g_AO);

    cudaFuncSetAttribute(flash_kernel,
                         cudaFuncAttributeMaxDynamicSharedMemorySize,
                         FLASH_SMEM_BYTES);

    dim3 gg(DD / 128, MM / 128);   // (16, 32)
    gemm_nt_kernel<true ><<<gg, 256>>>(x,  wq, Q,  fc, fs);
    gemm_nt_kernel<true ><<<gg, 256>>>(x,  wk, K,  fc, fs);
    gemm_nt_kernel<false><<<gg, 256>>>(x,  wv, V,  nullptr, nullptr);

    flash_kernel<<<dim3(SS / 64, BB * HH), 256, FLASH_SMEM_BYTES>>>(Q, K, V, AO);

    gemm_nt_kernel<false><<<gg, 256>>>(AO, wo, out, nullptr, nullptr);
}

// round 7
// speedup vs baseline: 3.1478x; 3.1478x over previous
#include <cuda_runtime.h>
#include <cuda_bf16.h>
#include <cstdint>

#define BB 2
#define SS 2048
#define DD 2048
#define HH 16
#define HD 128
#define HD2 64
#define MM (BB*SS)

// Scratch (device globals: allocation-free per harness rules)
__device__ float g_Q[(size_t)MM * DD];
__device__ float g_K[(size_t)MM * DD];
__device__ float g_V[(size_t)MM * DD];
__device__ float g_AO[(size_t)MM * DD];

// ===========================================================================
// helpers
// ===========================================================================
__device__ __forceinline__ uint32_t smem_u32(const void* p) {
    uint32_t a;
    asm("{ .reg .u64 t; cvta.to.shared.u64 t, %1; cvt.u32.u64 %0, t; }"
        : "=r"(a) : "l"(p));
    return a;
}

__device__ __forceinline__ void ldsm4(uint32_t& r0, uint32_t& r1,
                                      uint32_t& r2, uint32_t& r3, uint32_t addr) {
    asm volatile("ldmatrix.sync.aligned.m8n8.x4.shared.b16 {%0,%1,%2,%3}, [%4];"
                 : "=r"(r0), "=r"(r1), "=r"(r2), "=r"(r3) : "r"(addr));
}

__device__ __forceinline__ void ldsm4t(uint32_t& r0, uint32_t& r1,
                                       uint32_t& r2, uint32_t& r3, uint32_t addr) {
    asm volatile("ldmatrix.sync.aligned.m8n8.x4.trans.shared.b16 {%0,%1,%2,%3}, [%4];"
                 : "=r"(r0), "=r"(r1), "=r"(r2), "=r"(r3) : "r"(addr));
}

__device__ __forceinline__ void mma16816(float* c, const uint32_t* a,
                                         const uint32_t* b) {
    asm volatile(
        "mma.sync.aligned.m16n8k16.row.col.f32.bf16.bf16.f32 "
        "{%0,%1,%2,%3}, {%4,%5,%6,%7}, {%8,%9}, {%0,%1,%2,%3};"
        : "+f"(c[0]), "+f"(c[1]), "+f"(c[2]), "+f"(c[3])
        : "r"(a[0]), "r"(a[1]), "r"(a[2]), "r"(a[3]), "r"(b[0]), "r"(b[1]));
}

__device__ __forceinline__ void mma2(float* c0, float* c1, const uint32_t* a,
                                     uint32_t b00, uint32_t b01,
                                     uint32_t b10, uint32_t b11) {
    uint32_t b0[2] = {b00, b01};
    uint32_t b1[2] = {b10, b11};
    mma16816(c0, a, b0);
    mma16816(c1, a, b1);
}

__device__ __forceinline__ uint32_t pkbf(float a, float b) {
    __nv_bfloat162 t = __floats2bfloat162_rn(a, b);
    return *(uint32_t*)&t;
}

// convert float4 -> bf16 hi/lo pairs stored at H[idx..idx+3], L[idx..idx+3]
__device__ __forceinline__ void cvt_store(__nv_bfloat16* H, __nv_bfloat16* L,
                                          int idx, float4 v) {
    __nv_bfloat16 h0 = __float2bfloat16_rn(v.x);
    __nv_bfloat16 h1 = __float2bfloat16_rn(v.y);
    __nv_bfloat16 h2 = __float2bfloat16_rn(v.z);
    __nv_bfloat16 h3 = __float2bfloat16_rn(v.w);
    *(__nv_bfloat162*)&H[idx]     = __nv_bfloat162(h0, h1);
    *(__nv_bfloat162*)&H[idx + 2] = __nv_bfloat162(h2, h3);
    *(__nv_bfloat162*)&L[idx] = __nv_bfloat162(
        __float2bfloat16_rn(v.x - __bfloat162float(h0)),
        __float2bfloat16_rn(v.y - __bfloat162float(h1)));
    *(__nv_bfloat162*)&L[idx + 2] = __nv_bfloat162(
        __float2bfloat16_rn(v.z - __bfloat162float(h2)),
        __float2bfloat16_rn(v.w - __bfloat162float(h3)));
}

// ===========================================================================
// bf16-split tensor-core GEMM: C[M,N] = A[M,K] @ W[N,K]^T
// C = Ah*Bh + Ah*Bl + Al*Bh  (fp32-accurate to ~2e-5)
// CTA tile 128x128, BK=32, 256 threads (8 warps, 2Mx4N), warp tile 64x32.
// ===========================================================================
#define LDA 40   // smem row stride in bf16 elements (pad 32 -> 40)

template<bool ROT>
__global__ __launch_bounds__(256)
void gemm_mma_kernel(const float* __restrict__ A, const float* __restrict__ W,
                     float* __restrict__ C,
                     const float* __restrict__ fc, const float* __restrict__ fs)
{
    __shared__ __align__(16) __nv_bfloat16 sAh[128][LDA];
    __shared__ __align__(16) __nv_bfloat16 sAl[128][LDA];
    __shared__ __align__(16) __nv_bfloat16 sBh[128][LDA];
    __shared__ __align__(16) __nv_bfloat16 sBl[128][LDA];

    const int t    = threadIdx.x;
    const int warp = t >> 5;
    const int lane = t & 31;
    const int row0 = blockIdx.y * 128;
    const int col0 = blockIdx.x * 128;
    const int wm   = (warp >> 2) * 64;
    const int wn   = (warp & 3) * 32;

    const uint32_t uAh = smem_u32(sAh);
    const uint32_t uAl = smem_u32(sAl);
    const uint32_t uBh = smem_u32(sBh);
    const uint32_t uBl = smem_u32(sBl);

    const int l8 = lane & 7;
    const int g  = lane >> 3;
    const int a_row  = wm + (g & 1) * 8 + l8;
    const int a_koff = (g >> 1) * 8;
    const int b_row  = wn + (g >> 1) * 8 + l8;
    const int b_koff = (g & 1) * 8;

    const int lr = t >> 3;
    const int lc = (t & 7) << 2;

    float acc[4][4][4];
#pragma unroll
    for (int mi = 0; mi < 4; mi++)
#pragma unroll
        for (int ni = 0; ni < 4; ni++)
#pragma unroll
            for (int e = 0; e < 4; e++) acc[mi][ni][e] = 0.f;

    for (int chunk = 0; chunk < DD / 32; chunk++) {
        const int kk = chunk * 32;

        float4 av[4], bv[4];
#pragma unroll
        for (int i = 0; i < 4; i++) {
            const int r = lr + 32 * i;
            av[i] = *(const float4*)(A + (size_t)(row0 + r) * DD + kk + lc);
            bv[i] = *(const float4*)(W + (size_t)(col0 + r) * DD + kk + lc);
        }

        __syncthreads();
#pragma unroll
        for (int i = 0; i < 4; i++) {
            const int r = lr + 32 * i;
            cvt_store(&sAh[0][0], &sAl[0][0], r * LDA + lc, av[i]);
            cvt_store(&sBh[0][0], &sBl[0][0], r * LDA + lc, bv[i]);
        }
        __syncthreads();

#pragma unroll
        for (int kb = 0; kb < 32; kb += 16) {
            uint32_t bh[4][2], bl[4][2];
#pragma unroll
            for (int j = 0; j < 2; j++) {
                const uint32_t boff =
                    (uint32_t)(((b_row + j * 16) * LDA + kb + b_koff) * 2);
                uint32_t r0, r1, r2, r3;
                ldsm4(r0, r1, r2, r3, uBh + boff);
                bh[2*j][0] = r0; bh[2*j][1] = r1;
                bh[2*j+1][0] = r2; bh[2*j+1][1] = r3;
                ldsm4(r0, r1, r2, r3, uBl + boff);
                bl[2*j][0] = r0; bl[2*j][1] = r1;
                bl[2*j+1][0] = r2; bl[2*j+1][1] = r3;
            }

            uint32_t a[4][4];
#pragma unroll
            for (int mi = 0; mi < 4; mi++)
                ldsm4(a[mi][0], a[mi][1], a[mi][2], a[mi][3],
                      uAh + (uint32_t)(((a_row + mi * 16) * LDA + kb + a_koff) * 2));
#pragma unroll
            for (int mi = 0; mi < 4; mi++)
#pragma unroll
                for (int ni = 0; ni < 4; ni++)
                    mma16816(acc[mi][ni], a[mi], bh[ni]);
#pragma unroll
            for (int mi = 0; mi < 4; mi++)
#pragma unroll
                for (int ni = 0; ni < 4; ni++)
                    mma16816(acc[mi][ni], a[mi], bl[ni]);

#pragma unroll
            for (int mi = 0; mi < 4; mi++)
                ldsm4(a[mi][0], a[mi][1], a[mi][2], a[mi][3],
                      uAl + (uint32_t)(((a_row + mi * 16) * LDA + kb + a_koff) * 2));
#pragma unroll
            for (int mi = 0; mi < 4; mi++)
#pragma unroll
                for (int ni = 0; ni < 4; ni++)
                    mma16816(acc[mi][ni], a[mi], bh[ni]);
        }
    }

    const int qr = lane >> 2;
    const int qc = (lane & 3) << 1;
#pragma unroll
    for (int mi = 0; mi < 4; mi++) {
        const int m0 = row0 + wm + mi * 16 + qr;
        const int m1 = m0 + 8;
        const int s0 = m0 & (SS - 1);
        const int s1 = m1 & (SS - 1);
#pragma unroll
        for (int ni = 0; ni < 4; ni++) {
            const int n = col0 + wn + ni * 8 + qc;
            float c0 = acc[mi][ni][0], c1 = acc[mi][ni][1];
            float c2 = acc[mi][ni][2], c3 = acc[mi][ni][3];
            if (ROT) {
                const int p = (n & (HD - 1)) >> 1;
                const float ca = fc[(size_t)s0 * HD2 + p];
                const float sa = fs[(size_t)s0 * HD2 + p];
                const float cb = fc[(size_t)s1 * HD2 + p];
                const float sb = fs[(size_t)s1 * HD2 + p];
                float o0 = c0 * ca - c1 * sa;
                float o1 = c0 * sa + c1 * ca;
                float o2 = c2 * cb - c3 * sb;
                float o3 = c2 * sb + c3 * cb;
                c0 = o0; c1 = o1; c2 = o2; c3 = o3;
            }
            *(float2*)(C + (size_t)m0 * DD + n) = make_float2(c0, c1);
            *(float2*)(C + (size_t)m1 * DD + n) = make_float2(c2, c3);
        }
    }
}

// ===========================================================================
// Flash attention with mma.sync bf16-split (FA2-style register softmax).
// Q tile 128 rows, K/V tile 64, hd=128. 256 threads = 8 warps x 16 q-rows.
// ===========================================================================
#define LDF 136   // bf16 row stride for flash smem tiles
#define FL_SMEM_BYTES ((2*128*LDF + 4*64*LDF) * 2)

__global__ __launch_bounds__(256)
void flash_mma_kernel(const float* __restrict__ Q, const float* __restrict__ K,
                      const float* __restrict__ V, float* __restrict__ O)
{
    extern __shared__ __nv_bfloat16 fsm[];
    __nv_bfloat16* Qh = fsm;
    __nv_bfloat16* Ql = Qh + 128 * LDF;
    __nv_bfloat16* Kh = Ql + 128 * LDF;
    __nv_bfloat16* Kl = Kh + 64 * LDF;
    __nv_bfloat16* Vh = Kl + 64 * LDF;
    __nv_bfloat16* Vl = Vh + 64 * LDF;

    const uint32_t uQh = smem_u32(Qh), uQl = smem_u32(Ql);
    const uint32_t uKh = smem_u32(Kh), uKl = smem_u32(Kl);
    const uint32_t uVh = smem_u32(Vh), uVl = smem_u32(Vl);

    const int t    = threadIdx.x;
    const int warp = t >> 5;
    const int lane = t & 31;
    const int qt   = (SS / 128 - 1) - blockIdx.x;   // big tiles first
    const int q0   = qt * 128;
    const int bh_  = blockIdx.y;
    const int b    = bh_ >> 4, h = bh_ & 15;

    const size_t headoff = (size_t)b * SS * DD + (size_t)h * HD;
    const float* Qp = Q + headoff;
    const float* Kp = K + headoff;
    const float* Vp = V + headoff;
    float*       Op = O + headoff;

    const int wq = warp * 16;          // warp's q-row block
    const int l8 = lane & 7;
    const int g  = lane >> 3;
    const int qr  = lane >> 2;         // 0..7
    const int qc2 = (lane & 3) << 1;   // 0,2,4,6

    // A-frag (Q): rows wq + (g&1)*8 + l8, k-offset (g>>1)*8
    const int a_row  = wq + (g & 1) * 8 + l8;
    const int a_koff = (g >> 1) * 8;
    // B-frag (K, non-trans): rows (g>>1)*8 + l8 (+ j*16), k-offset (g&1)*8
    const int b_row  = (g >> 1) * 8 + l8;
    const int b_koff = (g & 1) * 8;
    // B-frag (V, trans): rows ks*16 + (g&1)*8 + l8, col nt*16 + (g>>1)*8
    const int v_rofs = (g & 1) * 8 + l8;
    const int v_cofs = (g >> 1) * 8;

    // load Q tile 128x128 -> Qh/Ql
    for (int f = t; f < 4096; f += 256) {
        const int r  = f >> 5;
        const int c4 = (f & 31) << 2;
        float4 v = *(const float4*)(Qp + (size_t)(q0 + r) * DD + c4);
        cvt_store(Qh, Ql, r * LDF + c4, v);
    }

    float o[16][4];
#pragma unroll
    for (int j = 0; j < 16; j++)
#pragma unroll
        for (int e = 0; e < 4; e++) o[j][e] = 0.f;
    float mA = -1e30f, mB = -1e30f, lA = 0.f, lB = 0.f;

    const float scale = 0.08838834764831845f;   // 1/sqrt(128)
    const int rowA = q0 + wq + qr;
    const int rowB = rowA + 8;
    const int kmax = 2 * qt + 2;

    for (int kt = 0; kt < kmax; kt++) {
        const int k0 = kt * 64;

        __syncthreads();   // previous iter done reading K/V smem
        for (int f = t; f < 2048; f += 256) {
            const int r  = f >> 5;
            const int c4 = (f & 31) << 2;
            float4 kv = *(const float4*)(Kp + (size_t)(k0 + r) * DD + c4);
            cvt_store(Kh, Kl, r * LDF + c4, kv);
            float4 vv = *(const float4*)(Vp + (size_t)(k0 + r) * DD + c4);
            cvt_store(Vh, Vl, r * LDF + c4, vv);
        }
        __syncthreads();

        // ---- S = Q @ K^T (warp: 16 x 64) ----
        float s[8][4];
#pragma unroll
        for (int n = 0; n < 8; n++)
#pragma unroll
            for (int e = 0; e < 4; e++) s[n][e] = 0.f;

#pragma unroll 2
        for (int ks = 0; ks < 8; ks++) {
            uint32_t aqh[4], aql[4];
            ldsm4(aqh[0], aqh[1], aqh[2], aqh[3],
                  uQh + (uint32_t)((a_row * LDF + ks * 16 + a_koff) * 2));
            ldsm4(aql[0], aql[1], aql[2], aql[3],
                  uQl + (uint32_t)((a_row * LDF + ks * 16 + a_koff) * 2));
#pragma unroll
            for (int j = 0; j < 4; j++) {
                const uint32_t boff =
                    (uint32_t)(((j * 16 + b_row) * LDF + ks * 16 + b_koff) * 2);
                uint32_t h0, h1, h2, h3, lo0, lo1, lo2, lo3;
                ldsm4(h0, h1, h2, h3, uKh + boff);
                ldsm4(lo0, lo1, lo2, lo3, uKl + boff);
                mma2(s[2*j], s[2*j+1], aqh, h0, h1, h2, h3);
                mma2(s[2*j], s[2*j+1], aqh, lo0, lo1, lo2, lo3);
                mma2(s[2*j], s[2*j+1], aql, h0, h1, h2, h3);
            }
        }

        // ---- scale + causal mask ----
        const bool needmask = (k0 + 63 > q0 + wq);
#pragma unroll
        for (int n = 0; n < 8; n++) {
            const int cg = k0 + n * 8 + qc2;
            s[n][0] *= scale; s[n][1] *= scale;
            s[n][2] *= scale; s[n][3] *= scale;
            if (needmask) {
                if (cg     > rowA) s[n][0] = -1e30f;
                if (cg + 1 > rowA) s[n][1] = -1e30f;
                if (cg     > rowB) s[n][2] = -1e30f;
                if (cg + 1 > rowB) s[n][3] = -1e30f;
            }
        }

        // ---- online softmax ----
        float mxA = -1e30f, mxB = -1e30f;
#pragma unroll
        for (int n = 0; n < 8; n++) {
            mxA = fmaxf(mxA, fmaxf(s[n][0], s[n][1]));
            mxB = fmaxf(mxB, fmaxf(s[n][2], s[n][3]));
        }
        mxA = fmaxf(mxA, __shfl_xor_sync(0xffffffffu, mxA, 1));
        mxA = fmaxf(mxA, __shfl_xor_sync(0xffffffffu, mxA, 2));
        mxB = fmaxf(mxB, __shfl_xor_sync(0xffffffffu, mxB, 1));
        mxB = fmaxf(mxB, __shfl_xor_sync(0xffffffffu, mxB, 2));

        const float mnA = fmaxf(mA, mxA);
        const float mnB = fmaxf(mB, mxB);
        const float alA = __expf(mA - mnA);
        const float alB = __expf(mB - mnB);
        mA = mnA; mB = mnB;

        uint32_t ph01[8], ph23[8], pl01[8], pl23[8];
        float smA = 0.f, smB = 0.f;
#pragma unroll
        for (int n = 0; n < 8; n++) {
            const float p0 = __expf(s[n][0] - mnA);
            const float p1 = __expf(s[n][1] - mnA);
            const float p2 = __expf(s[n][2] - mnB);
            const float p3 = __expf(s[n][3] - mnB);
            smA += p0 + p1; smB += p2 + p3;
            const __nv_bfloat16 h0 = __float2bfloat16_rn(p0);
            const __nv_bfloat16 h1 = __float2bfloat16_rn(p1);
            const __nv_bfloat16 h2 = __float2bfloat16_rn(p2);
            const __nv_bfloat16 h3 = __float2bfloat16_rn(p3);
            __nv_bfloat162 t01 = __nv_bfloat162(h0, h1);
            __nv_bfloat162 t23 = __nv_bfloat162(h2, h3);
            ph01[n] = *(uint32_t*)&t01;
            ph23[n] = *(uint32_t*)&t23;
            pl01[n] = pkbf(p0 - __bfloat162float(h0), p1 - __bfloat162float(h1));
            pl23[n] = pkbf(p2 - __bfloat162float(h2), p3 - __bfloat162float(h3));
        }
        smA += __shfl_xor_sync(0xffffffffu, smA, 1);
        smA += __shfl_xor_sync(0xffffffffu, smA, 2);
        smB += __shfl_xor_sync(0xffffffffu, smB, 1);
        smB += __shfl_xor_sync(0xffffffffu, smB, 2);
        lA = lA * alA + smA;
        lB = lB * alB + smB;

#pragma unroll
        for (int j = 0; j < 16; j++) {
            o[j][0] *= alA; o[j][1] *= alA;
            o[j][2] *= alB; o[j][3] *= alB;
        }

        // ---- O += P @ V ----
#pragma unroll
        for (int ks = 0; ks < 4; ks++) {
            uint32_t aph[4] = {ph01[2*ks], ph23[2*ks], ph01[2*ks+1], ph23[2*ks+1]};
            uint32_t apl[4] = {pl01[2*ks], pl23[2*ks], pl01[2*ks+1], pl23[2*ks+1]};
#pragma unroll
            for (int nt = 0; nt < 8; nt++) {
                const uint32_t voff = (uint32_t)(
                    ((ks * 16 + v_rofs) * LDF + nt * 16 + v_cofs) * 2);
                uint32_t h0, h1, h2, h3, lo0, lo1, lo2, lo3;
                ldsm4t(h0, h1, h2, h3, uVh + voff);
                ldsm4t(lo0, lo1, lo2, lo3, uVl + voff);
                mma2(o[2*nt], o[2*nt+1], aph, h0, h1, h2, h3);
                mma2(o[2*nt], o[2*nt+1], aph, lo0, lo1, lo2, lo3);
                mma2(o[2*nt], o[2*nt+1], apl, h0, h1, h2, h3);
            }
        }
    }

    // ---- epilogue ----
    const float invA = 1.f / lA;
    const float invB = 1.f / lB;
#pragma unroll
    for (int j = 0; j < 16; j++) {
        const int col = j * 8 + qc2;
        *(float2*)(Op + (size_t)rowA * DD + col) =
            make_float2(o[j][0] * invA, o[j][1] * invA);
        *(float2*)(Op + (size_t)rowB * DD + col) =
            make_float2(o[j][2] * invB, o[j][3] * invB);
    }
}

// ---------------------------------------------------------------------------
extern "C" void kernel_launch(void* const* d_in, const int* in_sizes, int n_in,
                              void* d_out, int out_size)
{
    const float* x  = (const float*)d_in[0];
    const float* fc = (const float*)d_in[1];
    const float* fs = (const float*)d_in[2];
    const float* wq = (const float*)d_in[3];
    const float* wk = (const float*)d_in[4];
    const float* wv = (const float*)d_in[5];
    const float* wo = (const float*)d_in[6];
    float* out = (float*)d_out;

    float *Q, *K, *V, *AO;
    cudaGetSymbolAddress((void**)&Q,  g_Q);
    cudaGetSymbolAddress((void**)&K,  g_K);
    cudaGetSymbolAddress((void**)&V,  g_V);
    cudaGetSymbolAddress((void**)&AO, g_AO);

    cudaFuncSetAttribute(flash_mma_kernel,
                         cudaFuncAttributeMaxDynamicSharedMemorySize, FL_SMEM_BYTES);

    dim3 gg(DD / 128, MM / 128);   // (16, 32)
    gemm_mma_kernel<true ><<<gg, 256>>>(x,  wq, Q,  fc, fs);
    gemm_mma_kernel<true ><<<gg, 256>>>(x,  wk, K,  fc, fs);
    gemm_mma_kernel<false><<<gg, 256>>>(x,  wv, V,  nullptr, nullptr);

    flash_mma_kernel<<<dim3(SS / 128, BB * HH), 256, FL_SMEM_BYTES>>>(Q, K, V, AO);

    gemm_mma_kernel<false><<<gg, 256>>>(AO, wo, out, nullptr, nullptr);
}